// round 1
// baseline (speedup 1.0000x reference)
#include <cuda_runtime.h>
#include <cuda_bf16.h>

typedef unsigned long long ull;

#define Nn 1024
#define Ff 64
#define Cc 4
#define Ee 32768
#define Hh 256

// ---------------- scratch (static __device__, no runtime alloc) ----------------
__device__ float4 g_adj[Nn * Nn];          // [i][j] -> 4 channel weights (16 MB)
__device__ float4 g_agg4[Cc * Nn * Ff / 4]; // agg[c][n][f] (1 MB)
__device__ float4 g_P4[Nn * Hh / 4];        // P[i][h] = x_next[i] @ We1[4:68] + be1
__device__ float4 g_Q4[Nn * Hh / 4];        // Q[j][h] = x_next[j] @ We1[68:132]

// ---------------- f32x2 helpers ----------------
__device__ __forceinline__ ull d_pack2(float a, float b) {
    ull r; asm("mov.b64 %0, {%1, %2};" : "=l"(r) : "f"(a), "f"(b)); return r;
}
__device__ __forceinline__ ull f2add(ull a, ull b) {
    ull r; asm("add.rn.f32x2 %0, %1, %2;" : "=l"(r) : "l"(a), "l"(b)); return r;
}
__device__ __forceinline__ ull f2fma(ull a, ull b, ull c) {
    ull r; asm("fma.rn.f32x2 %0, %1, %2, %3;" : "=l"(r) : "l"(a), "l"(b), "l"(c)); return r;
}
__device__ __forceinline__ ull f2relu(ull v) {
    float lo, hi;
    asm("mov.b64 {%0, %1}, %2;" : "=f"(lo), "=f"(hi) : "l"(v));
    lo = fmaxf(lo, 0.0f); hi = fmaxf(hi, 0.0f);
    ull r; asm("mov.b64 %0, {%1, %2};" : "=l"(r) : "f"(lo), "f"(hi)); return r;
}
__device__ __forceinline__ float f2sum(ull v) {
    float lo, hi;
    asm("mov.b64 {%0, %1}, %2;" : "=f"(lo), "=f"(hi) : "l"(v));
    return lo + hi;
}

// ---------------- K0: zero scratch ----------------
__global__ void zero_kernel() {
    int i = blockIdx.x * 256 + threadIdx.x;   // grid covers 1048576 threads
    float4 z = make_float4(0.f, 0.f, 0.f, 0.f);
    g_adj[i] = z;
    if (i < Cc * Nn * Ff / 4) g_agg4[i] = z;
}

// ---------------- K1: edge scatter (agg + dense adjacency) ----------------
__global__ void scatter_kernel(const float* __restrict__ x,
                               const int* __restrict__ ei,
                               const float* __restrict__ ew) {
    int g = blockIdx.x * 256 + threadIdx.x;   // C*E*64 threads
    int f = g & 63;
    int edge = g >> 6;                        // [0, 131072)
    int c = edge >> 15;
    int e = edge & (Ee - 1);
    int src = ei[c * 2 * Ee + e];             // ei[c][0][e]
    int tgt = ei[c * 2 * Ee + Ee + e];        // ei[c][1][e]
    float w = ew[(c << 15) + e];
    float* agg = (float*)g_agg4;
    atomicAdd(&agg[((c << 10) + tgt) * 64 + f], x[(src << 6) + f] * w);
    if (f == 0) {
        atomicAdd(&((float*)g_adj)[((src << 10) + tgt) * 4 + c], w);
    }
}

// ---------------- K2: fused node MLP -> x_next -> P/Q ----------------
// block handles 8 nodes, 256 threads
__global__ void __launch_bounds__(256) node_mlp_kernel(
    const float* __restrict__ x, const float* __restrict__ Wn1,
    const float* __restrict__ bn1, const float* __restrict__ Wn2,
    const float* __restrict__ bn2, const float* __restrict__ We1,
    const float* __restrict__ be1, const float* __restrict__ epsp) {
    __shared__ float h8[8][256];
    __shared__ float t18[8][256];
    __shared__ float xn8[8][64];
    const int tid = threadIdx.x;
    const int n0 = blockIdx.x * 8;
    const float oe = 1.0f + *epsp;
    const float* agg = (const float*)g_agg4;

    // h[n, c*64+f] = agg[c][n][f] + (1+eps)*x[n][f]
    for (int idx = tid; idx < 8 * 256; idx += 256) {
        int m = idx >> 8, t = idx & 255;
        int c = t >> 6, f = t & 63;
        int n = n0 + m;
        h8[m][t] = agg[((c << 10) + n) * 64 + f] + oe * x[(n << 6) + f];
    }
    __syncthreads();

    // t1 = relu(h @ Wn1 + bn1)
    {
        const int o = tid;
        float acc[8];
#pragma unroll
        for (int m = 0; m < 8; m++) acc[m] = bn1[o];
        for (int k = 0; k < 256; k++) {
            float wv = Wn1[(k << 8) + o];
#pragma unroll
            for (int m = 0; m < 8; m++) acc[m] = fmaf(h8[m][k], wv, acc[m]);
        }
#pragma unroll
        for (int m = 0; m < 8; m++) t18[m][o] = fmaxf(acc[m], 0.0f);
    }
    __syncthreads();

    // x_next = t1 @ Wn2 + bn2
    for (int idx = tid; idx < 512; idx += 256) {
        int m = idx >> 6, f = idx & 63;
        float acc = bn2[f];
        for (int k = 0; k < 256; k++)
            acc = fmaf(t18[m][k], Wn2[(k << 6) + f], acc);
        xn8[m][f] = acc;
    }
    __syncthreads();

    // P = x_next @ We1[4:68] + be1 ; Q = x_next @ We1[68:132]
    {
        const int o = tid;
        float pacc[8], qacc[8];
#pragma unroll
        for (int m = 0; m < 8; m++) { pacc[m] = be1[o]; qacc[m] = 0.f; }
        for (int f = 0; f < 64; f++) {
            float wa = We1[(4 + f) * 256 + o];
            float wb = We1[(68 + f) * 256 + o];
#pragma unroll
            for (int m = 0; m < 8; m++) {
                float xv = xn8[m][f];
                pacc[m] = fmaf(xv, wa, pacc[m]);
                qacc[m] = fmaf(xv, wb, qacc[m]);
            }
        }
        float* P = (float*)g_P4;
        float* Q = (float*)g_Q4;
#pragma unroll
        for (int m = 0; m < 8; m++) {
            P[((n0 + m) << 8) + o] = pacc[m];
            Q[((n0 + m) << 8) + o] = qacc[m];
        }
    }
}

// ---------------- K3: edge MLP over all (i,j) pairs ----------------
// block = 32 i x 32 j tile; 8 warps; warp w owns i_local w*4..w*4+3; lane = j_local
#define PQ_STRIDE 258
#define SMEM_BYTES (2 * 32 * PQ_STRIDE * 4 + 2 * 512 * 8 + 32 * 33 * 16)

__global__ void __launch_bounds__(256, 2) edge_mlp_kernel(
    const float* __restrict__ We1, const float* __restrict__ We2,
    const float* __restrict__ be2, float4* __restrict__ out) {
    extern __shared__ float smem[];
    float* Ps = smem;                              // [32][258]
    float* Qs = smem + 32 * PQ_STRIDE;             // [32][258]
    ull* W2P = (ull*)(smem + 2 * 32 * PQ_STRIDE);  // [4][128] packed (h,h+1)
    ull* W1P = W2P + 512;                          // [4][128] packed (h,h+1)
    float4* AdjS = (float4*)(W1P + 512);           // [32][33]

    const int tid = threadIdx.x;
    const int lane = tid & 31;
    const int wrp = tid >> 5;
    const int j0 = blockIdx.x << 5;
    const int i0 = blockIdx.y << 5;

    for (int idx = tid; idx < 32 * 64; idx += 256) {
        int r = idx >> 6, c4 = idx & 63;
        float4 pv = g_P4[((i0 + r) << 6) + c4];
        float4 qv = g_Q4[((j0 + r) << 6) + c4];
        float* pd = &Ps[r * PQ_STRIDE + (c4 << 2)];
        pd[0] = pv.x; pd[1] = pv.y; pd[2] = pv.z; pd[3] = pv.w;
        float* qd = &Qs[r * PQ_STRIDE + (c4 << 2)];
        qd[0] = qv.x; qd[1] = qv.y; qd[2] = qv.z; qd[3] = qv.w;
    }
    for (int idx = tid; idx < 512; idx += 256) {
        int k = idx >> 7, h2 = idx & 127;
        W2P[(k << 7) + h2] = d_pack2(We2[(h2 << 3) + k], We2[(h2 << 3) + 4 + k]);
        W1P[(k << 7) + h2] = d_pack2(We1[(k << 8) + (h2 << 1)], We1[(k << 8) + (h2 << 1) + 1]);
    }
    for (int idx = tid; idx < 1024; idx += 256) {
        int il = idx >> 5, jl = idx & 31;
        AdjS[il * 33 + jl] = g_adj[((i0 + il) << 10) + (j0 + jl)];
    }
    __syncthreads();

    const int ibase = wrp << 2;
    ull a2[4][4];
#pragma unroll
    for (int ii = 0; ii < 4; ii++) {
        float4 a = AdjS[(ibase + ii) * 33 + lane];
        a2[ii][0] = d_pack2(a.x, a.x);
        a2[ii][1] = d_pack2(a.y, a.y);
        a2[ii][2] = d_pack2(a.z, a.z);
        a2[ii][3] = d_pack2(a.w, a.w);
    }
    ull acc[4][4];
#pragma unroll
    for (int ii = 0; ii < 4; ii++)
#pragma unroll
        for (int k = 0; k < 4; k++) acc[ii][k] = 0ULL;

    const ull* Qrow = (const ull*)&Qs[lane * PQ_STRIDE];
#pragma unroll 2
    for (int h2 = 0; h2 < 128; h2++) {
        ull q = Qrow[h2];
        ull w20 = W2P[h2], w21 = W2P[128 + h2], w22 = W2P[256 + h2], w23 = W2P[384 + h2];
        ull w10 = W1P[h2], w11 = W1P[128 + h2], w12 = W1P[256 + h2], w13 = W1P[384 + h2];
#pragma unroll
        for (int ii = 0; ii < 4; ii++) {
            ull p = *(const ull*)&Ps[(ibase + ii) * PQ_STRIDE + (h2 << 1)];
            ull v = f2add(p, q);
            v = f2fma(a2[ii][0], w10, v);
            v = f2fma(a2[ii][1], w11, v);
            v = f2fma(a2[ii][2], w12, v);
            v = f2fma(a2[ii][3], w13, v);
            v = f2relu(v);
            acc[ii][0] = f2fma(v, w20, acc[ii][0]);
            acc[ii][1] = f2fma(v, w21, acc[ii][1]);
            acc[ii][2] = f2fma(v, w22, acc[ii][2]);
            acc[ii][3] = f2fma(v, w23, acc[ii][3]);
        }
    }
    const float b0 = be2[0], b1 = be2[1], b2 = be2[2], b3 = be2[3];
#pragma unroll
    for (int ii = 0; ii < 4; ii++) {
        float4 o;
        o.x = f2sum(acc[ii][0]) + b0;
        o.y = f2sum(acc[ii][1]) + b1;
        o.z = f2sum(acc[ii][2]) + b2;
        o.w = f2sum(acc[ii][3]) + b3;
        out[((i0 + ibase + ii) << 10) + j0 + lane] = o;
    }
}

// ---------------- launch ----------------
extern "C" void kernel_launch(void* const* d_in, const int* in_sizes, int n_in,
                              void* d_out, int out_size) {
    const float* x   = (const float*)d_in[0];
    const int*   ei  = (const int*)d_in[1];
    const float* ew  = (const float*)d_in[2];
    const float* Wn1 = (const float*)d_in[3];
    const float* bn1 = (const float*)d_in[4];
    const float* Wn2 = (const float*)d_in[5];
    const float* bn2 = (const float*)d_in[6];
    const float* We1 = (const float*)d_in[7];
    const float* be1 = (const float*)d_in[8];
    const float* We2 = (const float*)d_in[9];
    const float* be2 = (const float*)d_in[10];
    const float* eps = (const float*)d_in[11];
    float4* out = (float4*)d_out;

    zero_kernel<<<(Nn * Nn) / 256, 256>>>();
    scatter_kernel<<<(Cc * Ee * 64) / 256, 256>>>(x, ei, ew);
    node_mlp_kernel<<<Nn / 8, 256>>>(x, Wn1, bn1, Wn2, bn2, We1, be1, eps);

    cudaFuncSetAttribute(edge_mlp_kernel,
                         cudaFuncAttributeMaxDynamicSharedMemorySize, SMEM_BYTES);
    edge_mlp_kernel<<<dim3(32, 32), 256, SMEM_BYTES>>>(We1, We2, be2, out);
}